// round 10
// baseline (speedup 1.0000x reference)
#include <cuda_runtime.h>
#include <cuda_bf16.h>
#include <cuda_fp16.h>
#include <math.h>
#include <stdint.h>

#define BDIM 2048
#define TDIM 128
#define FDIM 128
#define HDIM 512
#define LDIM 8
#define KWIN 10
#define GATES 2064
#define H6 85
#define NPAD 2176            // GATES padded to 17*128
#define KPAD 640             // 128 (x) + 512 (h); dt handled as rank-1 in epilogue
#define NCHUNK 10            // KPAD / 64
#define CONVK 5120           // HDIM * KWIN
#define CONVCHUNK 80         // CONVK / 64
#define MTILE 128
#define NTILE 128
#define STEP_THREADS 128
#define WSCALE 64.0f
#define WINV  0.015625f
// step stage: A fp16 16K @0, B_hi fp16 16K @16384, B_lo fp16 16K @32768
#define BUF_BYTES 49152
#define SMEM_BYTES (2 * BUF_BYTES)     // 96KB/CTA, 2 CTAs/SM = 192KB
// conv kernel keeps bf16 3-pass 128x128 tiles
#define CBUF_BYTES 65536
#define CSMEM_BYTES (3 * CBUF_BYTES)

// ---------------- device globals (static; no runtime allocation) ---------------
__device__ __align__(256) __half g_Whi[(size_t)NPAD * KPAD];   // (W*64)^T hi, (N,K)
__device__ __align__(256) __half g_Wlo[(size_t)NPAD * KPAD];   // (W*64)^T lo
__device__ __align__(256) __half g_xT[(size_t)TDIM * BDIM * FDIM]; // x (T,B,F) fp16
__device__ __align__(256) __half g_h[BDIM * HDIM];             // hidden state fp16
__device__ __align__(256) __nv_bfloat16 g_lhhi[(size_t)BDIM * CONVK]; // local_h hi
__device__ __align__(256) __nv_bfloat16 g_lhlo[(size_t)BDIM * CONVK];
__device__ __align__(256) __nv_bfloat16 g_cwhi[(size_t)HDIM * CONVK]; // conv_w
__device__ __align__(256) __nv_bfloat16 g_cwlo[(size_t)HDIM * CONVK];
__device__ __align__(256) float g_dt[TDIM * BDIM];    // time transposed (T,B) fp32
__device__ __align__(256) float g_Wdt[NPAD];          // dt row (unscaled fp32)
__device__ __align__(256) float g_bc[NPAD];
__device__ __align__(256) float g_xo[(size_t)BDIM * NPAD];
__device__ __align__(256) float g_c[BDIM * HDIM];
__device__ __align__(256) float g_hring[KWIN * BDIM * HDIM];
__device__ __align__(256) float g_ldis[BDIM * KWIN];
__device__ __align__(256) float g_mh[BDIM * HDIM];
__device__ __align__(256) float g_t1[BDIM * H6];
__device__ __align__(256) float g_theme[BDIM * HDIM];

__device__ __forceinline__ float sigmoidf_(float x) { return 1.0f / (1.0f + expf(-x)); }

// ---------------- PTX helpers (compute_103-legal, sm_80-era) --------------------
__device__ __forceinline__ uint32_t smem_u32(const void* p) {
    uint32_t a;
    asm("{ .reg .u64 t; cvta.to.shared.u64 t, %1; cvt.u32.u64 %0, t; }" : "=r"(a) : "l"(p));
    return a;
}
__device__ __forceinline__ void cp16(uint32_t saddr, const void* g) {
    asm volatile("cp.async.cg.shared.global [%0], [%1], 16;" :: "r"(saddr), "l"(g)
                 : "memory");
}
#define CP_COMMIT() asm volatile("cp.async.commit_group;" ::: "memory")
#define CP_WAIT0()  asm volatile("cp.async.wait_group 0;" ::: "memory")
#define CP_WAIT1()  asm volatile("cp.async.wait_group 1;" ::: "memory")

__device__ __forceinline__ void ldsm_x4(uint32_t* r, uint32_t addr) {
    asm volatile("ldmatrix.sync.aligned.m8n8.x4.shared.b16 {%0,%1,%2,%3}, [%4];"
                 : "=r"(r[0]), "=r"(r[1]), "=r"(r[2]), "=r"(r[3]) : "r"(addr));
}
__device__ __forceinline__ void ldsm_x2(uint32_t* r, uint32_t addr) {
    asm volatile("ldmatrix.sync.aligned.m8n8.x2.shared.b16 {%0,%1}, [%2];"
                 : "=r"(r[0]), "=r"(r[1]) : "r"(addr));
}
__device__ __forceinline__ void mma_f16(float* d, const uint32_t* a, const uint32_t* b) {
    asm volatile(
        "mma.sync.aligned.m16n8k16.row.col.f32.f16.f16.f32 "
        "{%0,%1,%2,%3}, {%4,%5,%6,%7}, {%8,%9}, {%0,%1,%2,%3};"
        : "+f"(d[0]), "+f"(d[1]), "+f"(d[2]), "+f"(d[3])
        : "r"(a[0]), "r"(a[1]), "r"(a[2]), "r"(a[3]), "r"(b[0]), "r"(b[1]));
}
__device__ __forceinline__ void mma_bf16(float* d, const uint32_t* a, const uint32_t* b) {
    asm volatile(
        "mma.sync.aligned.m16n8k16.row.col.f32.bf16.bf16.f32 "
        "{%0,%1,%2,%3}, {%4,%5,%6,%7}, {%8,%9}, {%0,%1,%2,%3};"
        : "+f"(d[0]), "+f"(d[1]), "+f"(d[2]), "+f"(d[3])
        : "r"(a[0]), "r"(a[1]), "r"(a[2]), "r"(a[3]), "r"(b[0]), "r"(b[1]));
}

// ---------------- prep ----------------------------------------------------------
__global__ void prep_kernel(const float* __restrict__ x, const float* __restrict__ tmv,
                            const float* __restrict__ Wk, const float* __restrict__ bk,
                            const float* __restrict__ Wr, const float* __restrict__ br,
                            const float* __restrict__ conv_w) {
    size_t id = (size_t)blockIdx.x * blockDim.x + threadIdx.x;
    if (id < (size_t)NPAD * KPAD) {
        int n = (int)(id / KPAD), k = (int)(id % KPAD);
        float v = 0.0f;
        if (n < GATES)
            v = (k < FDIM) ? Wk[k * GATES + n] : Wr[(k - FDIM) * GATES + n];
        v *= WSCALE;                               // lift W_lo out of fp16 subnormals
        __half hi = __float2half_rn(v);
        g_Whi[id] = hi;
        g_Wlo[id] = __float2half_rn(v - __half2float(hi));
    }
    if (id < NPAD) {
        g_bc[id]  = (id < GATES) ? bk[id] + br[id] : 0.0f;
        g_Wdt[id] = (id < GATES) ? Wk[(size_t)FDIM * GATES + id] +
                                   Wr[(size_t)HDIM * GATES + id] : 0.0f;
    }
    if (id < (size_t)TDIM * BDIM * FDIM) {
        int f = (int)(id & (FDIM - 1));
        int b = (int)((id >> 7) & (BDIM - 1));
        int t = (int)(id >> 18);
        g_xT[id] = __float2half_rn(x[((size_t)b * TDIM + t) * FDIM + f]);
    }
    if (id < (size_t)TDIM * BDIM) {
        int b = (int)(id % BDIM), t = (int)(id / BDIM);
        g_dt[id] = tmv[(size_t)b * TDIM + t];
    }
    if (id < (size_t)BDIM * HDIM) {
        g_c[id] = 0.0f;
        g_h[id] = __float2half_rn(0.0f);
    }
    if (id < (size_t)HDIM * CONVK) {
        float v = conv_w[id];                       // already (512, 5120) K-major
        __nv_bfloat16 hi = __float2bfloat16(v);
        g_cwhi[id] = hi;
        g_cwlo[id] = __float2bfloat16(v - __bfloat162float(hi));
    }
}

// ---------------- step chunk loader (128 threads; 128xK A, 128xK B hi/lo) -------
__device__ __forceinline__ void step_load_chunk(uint32_t sb, int buf, int c, int t,
                                                int bm, int bn) {
    int tid = threadIdx.x;
    uint32_t base = sb + (uint32_t)buf * BUF_BYTES;
    // A: 128 rows x 64 fp16 = 1024 16B vectors
#pragma unroll
    for (int it = 0; it < 8; ++it) {
        int idx = tid + it * STEP_THREADS;
        int r = idx >> 3, s = idx & 7;
        uint32_t soff = (uint32_t)(r * 128 + ((s ^ (r & 7)) << 4));
        const __half* gp;
        if (c < 2)
            gp = g_xT + ((size_t)t * BDIM + bm + r) * FDIM + c * 64 + s * 8;
        else
            gp = g_h + (size_t)(bm + r) * HDIM + (c - 2) * 64 + s * 8;
        cp16(base + soff, gp);
    }
    // B hi/lo: 128 rows x 64 fp16 = 1024 vectors each
#pragma unroll
    for (int it = 0; it < 8; ++it) {
        int idx = tid + it * STEP_THREADS;
        int r = idx >> 3, s = idx & 7;
        uint32_t soff = (uint32_t)(r * 128 + ((s ^ (r & 7)) << 4));
        size_t go = (size_t)(bn + r) * KPAD + c * 64 + s * 8;
        cp16(base + 16384 + soff, g_Whi + go);
        cp16(base + 32768 + soff, g_Wlo + go);
    }
}

// ---------------- compute one K=64 chunk, 64x64 warp tile (2 passes) ------------
// 4 warps = 2 (m) x 2 (n). acc[mi=4][ni=8][4].
__device__ __forceinline__ void step_compute_chunk(uint32_t base, int warp_m, int warp_n,
                                                   int lane, float (*acc)[8][4]) {
    uint32_t Ab = base, Bhi = base + 16384, Blo = base + 32768;
    int arow_off = (lane & 7) + ((lane & 8) ? 8 : 0);
    int bL = lane & 15;
#pragma unroll
    for (int ks = 0; ks < 4; ++ks) {
        uint32_t ah[4][4];
        int aseg = 2 * ks + ((lane & 16) ? 1 : 0);
        int bseg = 2 * ks + ((bL & 8) ? 1 : 0);
#pragma unroll
        for (int mi = 0; mi < 4; ++mi) {
            int r = warp_m * 64 + mi * 16 + arow_off;
            uint32_t off = (uint32_t)(r * 128 + ((aseg ^ (r & 7)) << 4));
            ldsm_x4(ah[mi], Ab + off);
        }
#pragma unroll
        for (int ni = 0; ni < 8; ++ni) {
            uint32_t bh[2], bl_[2];
            int r = warp_n * 64 + ni * 8 + (bL & 7);
            uint32_t off = (uint32_t)(r * 128 + ((bseg ^ (r & 7)) << 4));
            ldsm_x2(bh, Bhi + off);
            ldsm_x2(bl_, Blo + off);
#pragma unroll
            for (int mi = 0; mi < 4; ++mi) mma_f16(acc[mi][ni], ah[mi], bh);
#pragma unroll
            for (int mi = 0; mi < 4; ++mi) mma_f16(acc[mi][ni], ah[mi], bl_);
        }
    }
}

// ---------------- per-step GEMM: xo = ([x_t|h] @ 64W)/64 + dt*Wdt + bc ----------
// Tile 128x128, 128 threads, grid (17, 16) = 272 CTAs, 2 CTAs/SM — independent
// barrier domains overlap each other's sync/epilogue bubbles on the tensor pipe.
__global__ void __launch_bounds__(STEP_THREADS, 2) step_mma_kernel(int t) {
    extern __shared__ char smem[];
    uint32_t sb = smem_u32(smem);
    int tid = threadIdx.x, wid = tid >> 5, lane = tid & 31;
    int warp_m = wid >> 1, warp_n = wid & 1;
    int bn = blockIdx.x * NTILE, bm = blockIdx.y * MTILE;

    float acc[4][8][4];
#pragma unroll
    for (int i = 0; i < 4; ++i)
#pragma unroll
        for (int j = 0; j < 8; ++j)
#pragma unroll
            for (int k = 0; k < 4; ++k) acc[i][j][k] = 0.0f;

    step_load_chunk(sb, 0, 0, t, bm, bn);
    CP_COMMIT();
    for (int c = 0; c < NCHUNK; ++c) {
        CP_WAIT0();
        __syncthreads();
        // safe to overwrite buffer (c+1)&1: all warps finished chunk c-1's compute
        if (c + 1 < NCHUNK) {
            step_load_chunk(sb, (c + 1) & 1, c + 1, t, bm, bn);
            CP_COMMIT();
        }
        step_compute_chunk(sb + (uint32_t)(c & 1) * BUF_BYTES, warp_m, warp_n, lane, acc);
    }

    // epilogue: acc/64 + bias + dt*Wdt -> g_xo
    int gr = lane >> 2, gc = (lane & 3) * 2;
#pragma unroll
    for (int mi = 0; mi < 4; ++mi) {
        int row0 = bm + warp_m * 64 + mi * 16 + gr;
        float dt0 = g_dt[t * BDIM + row0];
        float dt8 = g_dt[t * BDIM + row0 + 8];
#pragma unroll
        for (int ni = 0; ni < 8; ++ni) {
            int col = bn + warp_n * 64 + ni * 8 + gc;
            float b0 = g_bc[col], b1 = g_bc[col + 1];
            float w0 = g_Wdt[col], w1 = g_Wdt[col + 1];
            float2 v0 = make_float2(acc[mi][ni][0] * WINV + b0 + dt0 * w0,
                                    acc[mi][ni][1] * WINV + b1 + dt0 * w1);
            float2 v1 = make_float2(acc[mi][ni][2] * WINV + b0 + dt8 * w0,
                                    acc[mi][ni][3] * WINV + b1 + dt8 * w1);
            *(float2*)&g_xo[(size_t)row0 * NPAD + col] = v0;
            *(float2*)&g_xo[(size_t)(row0 + 8) * NPAD + col] = v1;
        }
    }
}

// ---------------- conv tail: bf16 3-pass, 128x128 tiles (grid 4x16) -------------
__device__ __forceinline__ void conv_load_chunk(uint32_t sb, int buf, int c,
                                                int bm, int bn) {
    int tid = threadIdx.x;
    uint32_t base = sb + (uint32_t)buf * CBUF_BYTES;
#pragma unroll
    for (int it = 0; it < 4; ++it) {
        int idx = tid + it * 256;
        int r = idx >> 3, s = idx & 7;
        uint32_t soff = (uint32_t)(r * 128 + ((s ^ (r & 7)) << 4));
        size_t go = (size_t)(bm + r) * CONVK + c * 64 + s * 8;
        cp16(base + soff, g_lhhi + go);
        cp16(base + 16384 + soff, g_lhlo + go);
    }
#pragma unroll
    for (int it = 0; it < 4; ++it) {
        int idx = tid + it * 256;
        int r = idx >> 3, s = idx & 7;
        uint32_t soff = (uint32_t)(r * 128 + ((s ^ (r & 7)) << 4));
        size_t go = (size_t)(bn + r) * CONVK + c * 64 + s * 8;
        cp16(base + 32768 + soff, g_cwhi + go);
        cp16(base + 49152 + soff, g_cwlo + go);
    }
}

__device__ __forceinline__ void conv_compute_chunk(uint32_t base, int warp_m, int warp_n,
                                                   int lane, float (*acc)[4][4]) {
    uint32_t Ahi = base, Alo = base + 16384, Bhi = base + 32768, Blo = base + 49152;
    int arow_off = (lane & 7) + ((lane & 8) ? 8 : 0);
    int bL = lane & 15;
#pragma unroll
    for (int ks = 0; ks < 4; ++ks) {
        uint32_t ah[4][4], al_[4][4], bh[4][2], bl_[4][2];
        int aseg = 2 * ks + ((lane & 16) ? 1 : 0);
        int bseg = 2 * ks + ((bL & 8) ? 1 : 0);
#pragma unroll
        for (int mi = 0; mi < 4; ++mi) {
            int r = warp_m * 64 + mi * 16 + arow_off;
            uint32_t off = (uint32_t)(r * 128 + ((aseg ^ (r & 7)) << 4));
            ldsm_x4(ah[mi], Ahi + off);
            ldsm_x4(al_[mi], Alo + off);
        }
#pragma unroll
        for (int ni = 0; ni < 4; ++ni) {
            int r = warp_n * 32 + ni * 8 + (bL & 7);
            uint32_t off = (uint32_t)(r * 128 + ((bseg ^ (r & 7)) << 4));
            ldsm_x2(bh[ni], Bhi + off);
            ldsm_x2(bl_[ni], Blo + off);
        }
#pragma unroll
        for (int mi = 0; mi < 4; ++mi)
#pragma unroll
            for (int ni = 0; ni < 4; ++ni) {
                mma_bf16(acc[mi][ni], ah[mi], bh[ni]);
                mma_bf16(acc[mi][ni], al_[mi], bh[ni]);
                mma_bf16(acc[mi][ni], ah[mi], bl_[ni]);
            }
    }
}

__global__ void __launch_bounds__(256, 1) conv_mma_kernel(const float* __restrict__ cb,
                                                          float* __restrict__ out) {
    extern __shared__ char smem[];
    uint32_t sb = smem_u32(smem);
    int tid = threadIdx.x, wid = tid >> 5, lane = tid & 31;
    int warp_m = wid >> 2, warp_n = wid & 3;
    int bn = blockIdx.x * 128, bm = blockIdx.y * 128;

    float acc[4][4][4];
#pragma unroll
    for (int i = 0; i < 4; ++i)
#pragma unroll
        for (int j = 0; j < 4; ++j)
#pragma unroll
            for (int k = 0; k < 4; ++k) acc[i][j][k] = 0.0f;

    conv_load_chunk(sb, 0, 0, bm, bn); CP_COMMIT();
    conv_load_chunk(sb, 1, 1, bm, bn); CP_COMMIT();
    for (int c = 0; c < CONVCHUNK; ++c) {
        if (c + 1 < CONVCHUNK) { CP_WAIT1(); } else { CP_WAIT0(); }
        __syncthreads();
        if (c + 2 < CONVCHUNK) {
            conv_load_chunk(sb, (c + 2) % 3, c + 2, bm, bn);
            CP_COMMIT();
        }
        conv_compute_chunk(sb + (uint32_t)(c % 3) * CBUF_BYTES, warp_m, warp_n, lane, acc);
    }

    int gr = lane >> 2, gc = (lane & 3) * 2;
#pragma unroll
    for (int mi = 0; mi < 4; ++mi) {
        int row0 = bm + warp_m * 64 + mi * 16 + gr;
#pragma unroll
        for (int ni = 0; ni < 4; ++ni) {
            int col = bn + warp_n * 32 + ni * 8 + gc;
            float b0 = cb[col], b1 = cb[col + 1];
            float2 v0, v1;
            v0.x = g_theme[(size_t)row0 * HDIM + col] * (acc[mi][ni][0] + b0);
            v0.y = g_theme[(size_t)row0 * HDIM + col + 1] * (acc[mi][ni][1] + b1);
            v1.x = g_theme[(size_t)(row0 + 8) * HDIM + col] * (acc[mi][ni][2] + b0);
            v1.y = g_theme[(size_t)(row0 + 8) * HDIM + col + 1] * (acc[mi][ni][3] + b1);
            *(float2*)&out[(size_t)row0 * HDIM + col] = v0;
            *(float2*)&out[(size_t)(row0 + 8) * HDIM + col] = v1;
        }
    }
}

// ---------------- per-step gating ------------------------------------------------
__global__ void gate_kernel(int t, float* __restrict__ dist_out) {
    int b = blockIdx.x;
    int tid = threadIdx.x;
    __shared__ float sfm[LDIM], sim[LDIM];
    const float* xo = g_xo + (size_t)b * NPAD;

    if (tid == 0) {
        float z[LDIM], m = -1e30f;
#pragma unroll
        for (int l = 0; l < LDIM; l++) { z[l] = xo[l]; m = fmaxf(m, z[l]); }
        float s = 0.0f;
#pragma unroll
        for (int l = 0; l < LDIM; l++) { z[l] = expf(z[l] - m); s += z[l]; }
        float inv = 1.0f / s, cs = 0.0f, dsum = 0.0f;
#pragma unroll
        for (int l = 0; l < LDIM; l++) { cs += z[l] * inv; sfm[l] = cs; dsum += cs; }
        dist_out[b] = 1.0f - dsum * (1.0f / LDIM);
    }
    if (tid == 32) {
        float z[LDIM], m = -1e30f;
#pragma unroll
        for (int l = 0; l < LDIM; l++) { z[l] = xo[LDIM + l]; m = fmaxf(m, z[l]); }
        float s = 0.0f;
#pragma unroll
        for (int l = 0; l < LDIM; l++) { z[l] = expf(z[l] - m); s += z[l]; }
        float inv = 1.0f / s, cs = 0.0f;
#pragma unroll
        for (int l = LDIM - 1; l >= 0; l--) { cs += z[l] * inv; sim[l] = cs; }
    }
    __syncthreads();

    float* hslot = g_hring + (size_t)(t % KWIN) * BDIM * HDIM;
    int base = b * HDIM;
    for (int idx = tid; idx < HDIM; idx += blockDim.x) {
        int l = idx >> 6;
        float f  = sigmoidf_(xo[16 + idx]);
        float ii = sigmoidf_(xo[16 + 512 + idx]);
        float oo = sigmoidf_(xo[16 + 1024 + idx]);
        float ci = tanhf(xo[16 + 1536 + idx]);
        float cl = g_c[base + idx];
        float fm = sfm[l], im = sim[l], ov = fm * im;
        float cn = ov * (f * cl + ii * ci) + (fm - ov) * cl + (im - ov) * ci;
        float hn = oo * tanhf(cn);
        g_c[base + idx] = cn;
        hslot[base + idx] = hn;
        g_h[base + idx] = __float2half_rn(hn);
    }
}

// ---------------- tail kernels ---------------------------------------------------
__global__ void ldis_kernel(const float* __restrict__ dist) {
    int b = blockIdx.x * blockDim.x + threadIdx.x;
    if (b >= BDIM) return;
    float v[KWIN], s = 0.0f;
#pragma unroll
    for (int k = 0; k < KWIN; k++) { s += dist[(size_t)(TDIM - KWIN + k) * BDIM + b]; v[k] = s; }
    float m = -1e30f;
#pragma unroll
    for (int k = 0; k < KWIN; k++) m = fmaxf(m, v[k]);
    float es = 0.0f;
#pragma unroll
    for (int k = 0; k < KWIN; k++) { v[k] = expf(v[k] - m); es += v[k]; }
    float inv = 1.0f / es;
#pragma unroll
    for (int k = 0; k < KWIN; k++) g_ldis[b * KWIN + k] = v[k] * inv;
}

// local_h (bf16 hi/lo, layout (B, h*KWIN+k)) + mean over k -> g_mh
__global__ void meanlh_kernel() {
    int id = blockIdx.x * blockDim.x + threadIdx.x;
    if (id >= BDIM * HDIM) return;
    int b = id >> 9;
    int hh = id & 511;
    float acc = 0.0f;
    size_t lbase = (size_t)b * CONVK + hh * KWIN;
#pragma unroll
    for (int k = 0; k < KWIN; k++) {
        int slot = (TDIM - KWIN + k) % KWIN;
        float hv = g_hring[(size_t)slot * BDIM * HDIM + id];
        float lv = hv * g_ldis[b * KWIN + k];
        __nv_bfloat16 hi = __float2bfloat16(lv);
        g_lhhi[lbase + k] = hi;
        g_lhlo[lbase + k] = __float2bfloat16(lv - __bfloat162float(hi));
        acc += lv;
    }
    g_mh[id] = acc * (1.0f / KWIN);
}

template <int EPI>
__global__ void __launch_bounds__(256) sgemm_kernel(
    const float* __restrict__ A, const float* __restrict__ W,
    const float* __restrict__ bias, float* __restrict__ out, int M, int N, int K)
{
    __shared__ float As[8][128];
    __shared__ float Bs[8][128];
    int tid = threadIdx.x;
    int bm = blockIdx.y * 128;
    int bn = blockIdx.x * 128;
    int ty = tid >> 4, tx = tid & 15;

    float acc[8][8];
#pragma unroll
    for (int i = 0; i < 8; i++)
#pragma unroll
        for (int j = 0; j < 8; j++) acc[i][j] = 0.0f;

    int aRow = tid >> 1, aK = (tid & 1) * 4;
    int bRow = tid >> 5, bCol = (tid & 31) * 4;

    for (int k0 = 0; k0 < K; k0 += 8) {
        int gm = bm + aRow;
#pragma unroll
        for (int j = 0; j < 4; j++) {
            int gk = k0 + aK + j;
            As[aK + j][aRow] = (gm < M && gk < K) ? A[(size_t)gm * K + gk] : 0.0f;
        }
        {
            int gk = k0 + bRow;
#pragma unroll
            for (int j = 0; j < 4; j++) {
                int gn = bn + bCol + j;
                Bs[bRow][bCol + j] = (gk < K && gn < N) ? W[(size_t)gk * N + gn] : 0.0f;
            }
        }
        __syncthreads();
#pragma unroll
        for (int kk = 0; kk < 8; kk++) {
            float a[8], bb[8];
#pragma unroll
            for (int i = 0; i < 8; i++) a[i] = As[kk][ty * 8 + i];
#pragma unroll
            for (int i = 0; i < 8; i++) bb[i] = Bs[kk][tx * 8 + i];
#pragma unroll
            for (int i = 0; i < 8; i++)
#pragma unroll
                for (int j = 0; j < 8; j++) acc[i][j] += a[i] * bb[j];
        }
        __syncthreads();
    }
#pragma unroll
    for (int i = 0; i < 8; i++) {
        int gm = bm + ty * 8 + i;
        if (gm >= M) continue;
#pragma unroll
        for (int j = 0; j < 8; j++) {
            int gn = bn + tx * 8 + j;
            if (gn >= N) continue;
            float v = acc[i][j] + bias[gn];
            if (EPI == 1) v = fmaxf(v, 0.0f);
            if (EPI == 2) v = 1.0f / (1.0f + expf(-v));
            out[(size_t)gm * N + gn] = v;
        }
    }
}

// ---------------- host launcher --------------------------------------------------
extern "C" void kernel_launch(void* const* d_in, const int* in_sizes, int n_in,
                              void* d_out, int out_size) {
    const float* x      = (const float*)d_in[0];
    const float* tmv    = (const float*)d_in[1];
    const float* Wk     = (const float*)d_in[2];
    const float* bk     = (const float*)d_in[3];
    const float* Wr     = (const float*)d_in[4];
    const float* br     = (const float*)d_in[5];
    const float* Ws     = (const float*)d_in[6];
    const float* bs     = (const float*)d_in[7];
    const float* Wrs    = (const float*)d_in[8];
    const float* brs    = (const float*)d_in[9];
    const float* conv_w = (const float*)d_in[10];
    const float* conv_b = (const float*)d_in[11];
    float* out = (float*)d_out;
    float* dist_out = out + (size_t)BDIM * HDIM;   // distance region: (T, B)

    float *p_mh, *p_t1, *p_theme;
    cudaGetSymbolAddress((void**)&p_mh, g_mh);
    cudaGetSymbolAddress((void**)&p_t1, g_t1);
    cudaGetSymbolAddress((void**)&p_theme, g_theme);

    cudaFuncSetAttribute(step_mma_kernel, cudaFuncAttributeMaxDynamicSharedMemorySize,
                         SMEM_BYTES);
    cudaFuncSetAttribute(conv_mma_kernel, cudaFuncAttributeMaxDynamicSharedMemorySize,
                         CSMEM_BYTES);

    // prep (largest id space: T*B*F = 33.5M)
    size_t prep_total = (size_t)TDIM * BDIM * FDIM;
    prep_kernel<<<(unsigned)((prep_total + 255) / 256), 256>>>(x, tmv, Wk, bk, Wr, br,
                                                               conv_w);

    // recurrent scan: step GEMM (272 CTAs, 2/SM) + gating
    dim3 gstep(NPAD / NTILE, BDIM / MTILE);   // (17, 16)
    for (int t = 0; t < TDIM; t++) {
        step_mma_kernel<<<gstep, STEP_THREADS, SMEM_BYTES>>>(t);
        gate_kernel<<<BDIM, 256>>>(t, dist_out + (size_t)t * BDIM);
    }

    // tail
    ldis_kernel<<<(BDIM + 255) / 256, 256>>>(dist_out);
    meanlh_kernel<<<(BDIM * HDIM) / 256, 256>>>();
    sgemm_kernel<1><<<dim3(1, 16), 256>>>(p_mh, Ws, bs, p_t1, BDIM, H6, HDIM);
    sgemm_kernel<2><<<dim3(4, 16), 256>>>(p_t1, Wrs, brs, p_theme, BDIM, HDIM, H6);
    conv_mma_kernel<<<dim3(HDIM / 128, BDIM / 128), 256, CSMEM_BYTES>>>(conv_b, out);
}

// round 11
// speedup vs baseline: 1.2120x; 1.2120x over previous
#include <cuda_runtime.h>
#include <cuda_bf16.h>
#include <cuda_fp16.h>
#include <math.h>
#include <stdint.h>

#define BDIM 2048
#define TDIM 128
#define FDIM 128
#define HDIM 512
#define LDIM 8
#define KWIN 10
#define GATES 2064
#define H6 85
#define NPAD 2176            // GATES padded to 17*128
#define KPAD 640             // 128 (x) + 512 (h); dt handled as rank-1 in epilogue
#define NCHUNK 10            // KPAD / 64
#define CONVK 5120           // HDIM * KWIN
#define CONVCHUNK 80         // CONVK / 64
#define MTILE 256
#define NTILE 128
// step stage: A fp16 32K @0, B fp16 16K @32768   (single-pass fp16)
#define BUF_BYTES 49152
#define NSTAGE 3
#define SMEM_BYTES (NSTAGE * BUF_BYTES)
// conv kernel keeps bf16 3-pass 128x128 tiles
#define CBUF_BYTES 65536
#define CSMEM_BYTES (3 * CBUF_BYTES)

// ---------------- device globals (static; no runtime allocation) ---------------
__device__ __align__(256) __half g_W[(size_t)NPAD * KPAD];     // W^T fp16, (N,K)
__device__ __align__(256) __half g_xT[(size_t)TDIM * BDIM * FDIM]; // x (T,B,F) fp16
__device__ __align__(256) __half g_h[BDIM * HDIM];             // hidden state fp16
__device__ __align__(256) __nv_bfloat16 g_lhhi[(size_t)BDIM * CONVK]; // local_h hi
__device__ __align__(256) __nv_bfloat16 g_lhlo[(size_t)BDIM * CONVK];
__device__ __align__(256) __nv_bfloat16 g_cwhi[(size_t)HDIM * CONVK]; // conv_w
__device__ __align__(256) __nv_bfloat16 g_cwlo[(size_t)HDIM * CONVK];
__device__ __align__(256) float g_dt[TDIM * BDIM];    // time transposed (T,B) fp32
__device__ __align__(256) float g_Wdt[NPAD];          // dt row fp32
__device__ __align__(256) float g_bc[NPAD];
__device__ __align__(256) float g_xo[(size_t)BDIM * NPAD];
__device__ __align__(256) float g_c[BDIM * HDIM];
__device__ __align__(256) float g_hring[KWIN * BDIM * HDIM];
__device__ __align__(256) float g_ldis[BDIM * KWIN];
__device__ __align__(256) float g_mh[BDIM * HDIM];
__device__ __align__(256) float g_t1[BDIM * H6];
__device__ __align__(256) float g_theme[BDIM * HDIM];

__device__ __forceinline__ float fsig(float x) { return 1.0f / (1.0f + __expf(-x)); }
__device__ __forceinline__ float ftanh(float x) {
    return 1.0f - 2.0f / (__expf(2.0f * x) + 1.0f);
}

// ---------------- PTX helpers (compute_103-legal, sm_80-era) --------------------
__device__ __forceinline__ uint32_t smem_u32(const void* p) {
    uint32_t a;
    asm("{ .reg .u64 t; cvta.to.shared.u64 t, %1; cvt.u32.u64 %0, t; }" : "=r"(a) : "l"(p));
    return a;
}
__device__ __forceinline__ void cp16(uint32_t saddr, const void* g) {
    asm volatile("cp.async.cg.shared.global [%0], [%1], 16;" :: "r"(saddr), "l"(g)
                 : "memory");
}
#define CP_COMMIT() asm volatile("cp.async.commit_group;" ::: "memory")
#define CP_WAIT0()  asm volatile("cp.async.wait_group 0;" ::: "memory")
#define CP_WAIT1()  asm volatile("cp.async.wait_group 1;" ::: "memory")

__device__ __forceinline__ void ldsm_x4(uint32_t* r, uint32_t addr) {
    asm volatile("ldmatrix.sync.aligned.m8n8.x4.shared.b16 {%0,%1,%2,%3}, [%4];"
                 : "=r"(r[0]), "=r"(r[1]), "=r"(r[2]), "=r"(r[3]) : "r"(addr));
}
__device__ __forceinline__ void ldsm_x2(uint32_t* r, uint32_t addr) {
    asm volatile("ldmatrix.sync.aligned.m8n8.x2.shared.b16 {%0,%1}, [%2];"
                 : "=r"(r[0]), "=r"(r[1]) : "r"(addr));
}
__device__ __forceinline__ void mma_f16(float* d, const uint32_t* a, const uint32_t* b) {
    asm volatile(
        "mma.sync.aligned.m16n8k16.row.col.f32.f16.f16.f32 "
        "{%0,%1,%2,%3}, {%4,%5,%6,%7}, {%8,%9}, {%0,%1,%2,%3};"
        : "+f"(d[0]), "+f"(d[1]), "+f"(d[2]), "+f"(d[3])
        : "r"(a[0]), "r"(a[1]), "r"(a[2]), "r"(a[3]), "r"(b[0]), "r"(b[1]));
}
__device__ __forceinline__ void mma_bf16(float* d, const uint32_t* a, const uint32_t* b) {
    asm volatile(
        "mma.sync.aligned.m16n8k16.row.col.f32.bf16.bf16.f32 "
        "{%0,%1,%2,%3}, {%4,%5,%6,%7}, {%8,%9}, {%0,%1,%2,%3};"
        : "+f"(d[0]), "+f"(d[1]), "+f"(d[2]), "+f"(d[3])
        : "r"(a[0]), "r"(a[1]), "r"(a[2]), "r"(a[3]), "r"(b[0]), "r"(b[1]));
}

// ---------------- prep ----------------------------------------------------------
__global__ void prep_kernel(const float* __restrict__ x, const float* __restrict__ tmv,
                            const float* __restrict__ Wk, const float* __restrict__ bk,
                            const float* __restrict__ Wr, const float* __restrict__ br,
                            const float* __restrict__ conv_w) {
    size_t id = (size_t)blockIdx.x * blockDim.x + threadIdx.x;
    if (id < (size_t)NPAD * KPAD) {
        int n = (int)(id / KPAD), k = (int)(id % KPAD);
        float v = 0.0f;
        if (n < GATES)
            v = (k < FDIM) ? Wk[k * GATES + n] : Wr[(k - FDIM) * GATES + n];
        g_W[id] = __float2half_rn(v);
    }
    if (id < NPAD) {
        g_bc[id]  = (id < GATES) ? bk[id] + br[id] : 0.0f;
        g_Wdt[id] = (id < GATES) ? Wk[(size_t)FDIM * GATES + id] +
                                   Wr[(size_t)HDIM * GATES + id] : 0.0f;
    }
    if (id < (size_t)TDIM * BDIM * FDIM) {
        int f = (int)(id & (FDIM - 1));
        int b = (int)((id >> 7) & (BDIM - 1));
        int t = (int)(id >> 18);
        g_xT[id] = __float2half_rn(x[((size_t)b * TDIM + t) * FDIM + f]);
    }
    if (id < (size_t)TDIM * BDIM) {
        int b = (int)(id % BDIM), t = (int)(id / BDIM);
        g_dt[id] = tmv[(size_t)b * TDIM + t];
    }
    if (id < (size_t)BDIM * HDIM) {
        g_c[id] = 0.0f;
        g_h[id] = __float2half_rn(0.0f);
    }
    if (id < (size_t)HDIM * CONVK) {
        float v = conv_w[id];                       // already (512, 5120) K-major
        __nv_bfloat16 hi = __float2bfloat16(v);
        g_cwhi[id] = hi;
        g_cwlo[id] = __float2bfloat16(v - __bfloat162float(hi));
    }
}

// ---------------- step chunk loader (256 threads; 256xK A, 128xK B) -------------
__device__ __forceinline__ void step_load_chunk(uint32_t sb, int buf, int c, int t,
                                                int bm, int bn) {
    int tid = threadIdx.x;
    uint32_t base = sb + (uint32_t)buf * BUF_BYTES;
    // A: 256 rows x 64 fp16 = 2048 16B vectors
#pragma unroll
    for (int it = 0; it < 8; ++it) {
        int idx = tid + it * 256;
        int r = idx >> 3, s = idx & 7;
        uint32_t soff = (uint32_t)(r * 128 + ((s ^ (r & 7)) << 4));
        const __half* gp;
        if (c < 2)
            gp = g_xT + ((size_t)t * BDIM + bm + r) * FDIM + c * 64 + s * 8;
        else
            gp = g_h + (size_t)(bm + r) * HDIM + (c - 2) * 64 + s * 8;
        cp16(base + soff, gp);
    }
    // B: 128 rows x 64 fp16 = 1024 vectors
#pragma unroll
    for (int it = 0; it < 4; ++it) {
        int idx = tid + it * 256;
        int r = idx >> 3, s = idx & 7;
        uint32_t soff = (uint32_t)(r * 128 + ((s ^ (r & 7)) << 4));
        size_t go = (size_t)(bn + r) * KPAD + c * 64 + s * 8;
        cp16(base + 32768 + soff, g_W + go);
    }
}

// ---------------- compute one K=64 chunk, 64x64 warp tile (single pass) ---------
// 8 warps = 4 (m) x 2 (n). acc[mi=4][ni=8][4].
__device__ __forceinline__ void step_compute_chunk(uint32_t base, int warp_m, int warp_n,
                                                   int lane, float (*acc)[8][4]) {
    uint32_t Ab = base, Bb = base + 32768;
    int arow_off = (lane & 7) + ((lane & 8) ? 8 : 0);
    int bL = lane & 15;
#pragma unroll
    for (int ks = 0; ks < 4; ++ks) {
        uint32_t ah[4][4];
        int aseg = 2 * ks + ((lane & 16) ? 1 : 0);
        int bseg = 2 * ks + ((bL & 8) ? 1 : 0);
#pragma unroll
        for (int mi = 0; mi < 4; ++mi) {
            int r = warp_m * 64 + mi * 16 + arow_off;
            uint32_t off = (uint32_t)(r * 128 + ((aseg ^ (r & 7)) << 4));
            ldsm_x4(ah[mi], Ab + off);
        }
#pragma unroll
        for (int ni = 0; ni < 8; ++ni) {
            uint32_t bb[2];
            int r = warp_n * 64 + ni * 8 + (bL & 7);
            uint32_t off = (uint32_t)(r * 128 + ((bseg ^ (r & 7)) << 4));
            ldsm_x2(bb, Bb + off);
#pragma unroll
            for (int mi = 0; mi < 4; ++mi) mma_f16(acc[mi][ni], ah[mi], bb);
        }
    }
}

// ---------------- per-step GEMM: xo = [x_t|h] @ W + dt*Wdt + bc -----------------
// Tile 256x128, 256 threads, grid (17, 8) = 136 CTAs; 3-stage cp.async pipeline.
__global__ void __launch_bounds__(256, 1) step_mma_kernel(int t) {
    extern __shared__ char smem[];
    uint32_t sb = smem_u32(smem);
    int tid = threadIdx.x, wid = tid >> 5, lane = tid & 31;
    int warp_m = wid >> 1, warp_n = wid & 1;
    int bn = blockIdx.x * NTILE, bm = blockIdx.y * MTILE;

    float acc[4][8][4];
#pragma unroll
    for (int i = 0; i < 4; ++i)
#pragma unroll
        for (int j = 0; j < 8; ++j)
#pragma unroll
            for (int k = 0; k < 4; ++k) acc[i][j][k] = 0.0f;

    step_load_chunk(sb, 0, 0, t, bm, bn); CP_COMMIT();
    step_load_chunk(sb, 1, 1, t, bm, bn); CP_COMMIT();
    for (int c = 0; c < NCHUNK; ++c) {
        if (c + 1 < NCHUNK) { CP_WAIT1(); } else { CP_WAIT0(); }
        __syncthreads();
        // safe to overwrite stage (c+2)%3 == (c-1)%3: compute(c-1) done pre-barrier
        if (c + 2 < NCHUNK) {
            step_load_chunk(sb, (c + 2) % NSTAGE, c + 2, t, bm, bn);
            CP_COMMIT();
        }
        step_compute_chunk(sb + (uint32_t)(c % NSTAGE) * BUF_BYTES, warp_m, warp_n,
                           lane, acc);
    }

    // epilogue: acc + bias + dt*Wdt -> g_xo
    int gr = lane >> 2, gc = (lane & 3) * 2;
#pragma unroll
    for (int mi = 0; mi < 4; ++mi) {
        int row0 = bm + warp_m * 64 + mi * 16 + gr;
        float dt0 = g_dt[t * BDIM + row0];
        float dt8 = g_dt[t * BDIM + row0 + 8];
#pragma unroll
        for (int ni = 0; ni < 8; ++ni) {
            int col = bn + warp_n * 64 + ni * 8 + gc;
            float b0 = g_bc[col], b1 = g_bc[col + 1];
            float w0 = g_Wdt[col], w1 = g_Wdt[col + 1];
            float2 v0 = make_float2(acc[mi][ni][0] + b0 + dt0 * w0,
                                    acc[mi][ni][1] + b1 + dt0 * w1);
            float2 v1 = make_float2(acc[mi][ni][2] + b0 + dt8 * w0,
                                    acc[mi][ni][3] + b1 + dt8 * w1);
            *(float2*)&g_xo[(size_t)row0 * NPAD + col] = v0;
            *(float2*)&g_xo[(size_t)(row0 + 8) * NPAD + col] = v1;
        }
    }
}

// ---------------- conv tail: bf16 3-pass, 128x128 tiles (grid 4x16) -------------
__device__ __forceinline__ void conv_load_chunk(uint32_t sb, int buf, int c,
                                                int bm, int bn) {
    int tid = threadIdx.x;
    uint32_t base = sb + (uint32_t)buf * CBUF_BYTES;
#pragma unroll
    for (int it = 0; it < 4; ++it) {
        int idx = tid + it * 256;
        int r = idx >> 3, s = idx & 7;
        uint32_t soff = (uint32_t)(r * 128 + ((s ^ (r & 7)) << 4));
        size_t go = (size_t)(bm + r) * CONVK + c * 64 + s * 8;
        cp16(base + soff, g_lhhi + go);
        cp16(base + 16384 + soff, g_lhlo + go);
    }
#pragma unroll
    for (int it = 0; it < 4; ++it) {
        int idx = tid + it * 256;
        int r = idx >> 3, s = idx & 7;
        uint32_t soff = (uint32_t)(r * 128 + ((s ^ (r & 7)) << 4));
        size_t go = (size_t)(bn + r) * CONVK + c * 64 + s * 8;
        cp16(base + 32768 + soff, g_cwhi + go);
        cp16(base + 49152 + soff, g_cwlo + go);
    }
}

__device__ __forceinline__ void conv_compute_chunk(uint32_t base, int warp_m, int warp_n,
                                                   int lane, float (*acc)[4][4]) {
    uint32_t Ahi = base, Alo = base + 16384, Bhi = base + 32768, Blo = base + 49152;
    int arow_off = (lane & 7) + ((lane & 8) ? 8 : 0);
    int bL = lane & 15;
#pragma unroll
    for (int ks = 0; ks < 4; ++ks) {
        uint32_t ah[4][4], al_[4][4], bh[4][2], bl_[4][2];
        int aseg = 2 * ks + ((lane & 16) ? 1 : 0);
        int bseg = 2 * ks + ((bL & 8) ? 1 : 0);
#pragma unroll
        for (int mi = 0; mi < 4; ++mi) {
            int r = warp_m * 64 + mi * 16 + arow_off;
            uint32_t off = (uint32_t)(r * 128 + ((aseg ^ (r & 7)) << 4));
            ldsm_x4(ah[mi], Ahi + off);
            ldsm_x4(al_[mi], Alo + off);
        }
#pragma unroll
        for (int ni = 0; ni < 4; ++ni) {
            int r = warp_n * 32 + ni * 8 + (bL & 7);
            uint32_t off = (uint32_t)(r * 128 + ((bseg ^ (r & 7)) << 4));
            ldsm_x2(bh[ni], Bhi + off);
            ldsm_x2(bl_[ni], Blo + off);
        }
#pragma unroll
        for (int mi = 0; mi < 4; ++mi)
#pragma unroll
            for (int ni = 0; ni < 4; ++ni) {
                mma_bf16(acc[mi][ni], ah[mi], bh[ni]);
                mma_bf16(acc[mi][ni], al_[mi], bh[ni]);
                mma_bf16(acc[mi][ni], ah[mi], bl_[ni]);
            }
    }
}

__global__ void __launch_bounds__(256, 1) conv_mma_kernel(const float* __restrict__ cb,
                                                          float* __restrict__ out) {
    extern __shared__ char smem[];
    uint32_t sb = smem_u32(smem);
    int tid = threadIdx.x, wid = tid >> 5, lane = tid & 31;
    int warp_m = wid >> 2, warp_n = wid & 3;
    int bn = blockIdx.x * 128, bm = blockIdx.y * 128;

    float acc[4][4][4];
#pragma unroll
    for (int i = 0; i < 4; ++i)
#pragma unroll
        for (int j = 0; j < 4; ++j)
#pragma unroll
            for (int k = 0; k < 4; ++k) acc[i][j][k] = 0.0f;

    conv_load_chunk(sb, 0, 0, bm, bn); CP_COMMIT();
    conv_load_chunk(sb, 1, 1, bm, bn); CP_COMMIT();
    for (int c = 0; c < CONVCHUNK; ++c) {
        if (c + 1 < CONVCHUNK) { CP_WAIT1(); } else { CP_WAIT0(); }
        __syncthreads();
        if (c + 2 < CONVCHUNK) {
            conv_load_chunk(sb, (c + 2) % 3, c + 2, bm, bn);
            CP_COMMIT();
        }
        conv_compute_chunk(sb + (uint32_t)(c % 3) * CBUF_BYTES, warp_m, warp_n, lane, acc);
    }

    int gr = lane >> 2, gc = (lane & 3) * 2;
#pragma unroll
    for (int mi = 0; mi < 4; ++mi) {
        int row0 = bm + warp_m * 64 + mi * 16 + gr;
#pragma unroll
        for (int ni = 0; ni < 4; ++ni) {
            int col = bn + warp_n * 32 + ni * 8 + gc;
            float b0 = cb[col], b1 = cb[col + 1];
            float2 v0, v1;
            v0.x = g_theme[(size_t)row0 * HDIM + col] * (acc[mi][ni][0] + b0);
            v0.y = g_theme[(size_t)row0 * HDIM + col + 1] * (acc[mi][ni][1] + b1);
            v1.x = g_theme[(size_t)(row0 + 8) * HDIM + col] * (acc[mi][ni][2] + b0);
            v1.y = g_theme[(size_t)(row0 + 8) * HDIM + col + 1] * (acc[mi][ni][3] + b1);
            *(float2*)&out[(size_t)row0 * HDIM + col] = v0;
            *(float2*)&out[(size_t)(row0 + 8) * HDIM + col] = v1;
        }
    }
}

// ---------------- per-step gating (fast-math MUFU transcendental paths) ---------
__global__ void gate_kernel(int t, float* __restrict__ dist_out) {
    int b = blockIdx.x;
    int tid = threadIdx.x;
    __shared__ float sfm[LDIM], sim[LDIM];
    const float* xo = g_xo + (size_t)b * NPAD;

    if (tid == 0) {
        float z[LDIM], m = -1e30f;
#pragma unroll
        for (int l = 0; l < LDIM; l++) { z[l] = xo[l]; m = fmaxf(m, z[l]); }
        float s = 0.0f;
#pragma unroll
        for (int l = 0; l < LDIM; l++) { z[l] = __expf(z[l] - m); s += z[l]; }
        float inv = 1.0f / s, cs = 0.0f, dsum = 0.0f;
#pragma unroll
        for (int l = 0; l < LDIM; l++) { cs += z[l] * inv; sfm[l] = cs; dsum += cs; }
        dist_out[b] = 1.0f - dsum * (1.0f / LDIM);
    }
    if (tid == 32) {
        float z[LDIM], m = -1e30f;
#pragma unroll
        for (int l = 0; l < LDIM; l++) { z[l] = xo[LDIM + l]; m = fmaxf(m, z[l]); }
        float s = 0.0f;
#pragma unroll
        for (int l = 0; l < LDIM; l++) { z[l] = __expf(z[l] - m); s += z[l]; }
        float inv = 1.0f / s, cs = 0.0f;
#pragma unroll
        for (int l = LDIM - 1; l >= 0; l--) { cs += z[l] * inv; sim[l] = cs; }
    }
    __syncthreads();

    float* hslot = g_hring + (size_t)(t % KWIN) * BDIM * HDIM;
    int base = b * HDIM;
    for (int idx = tid; idx < HDIM; idx += blockDim.x) {
        int l = idx >> 6;
        float f  = fsig(xo[16 + idx]);
        float ii = fsig(xo[16 + 512 + idx]);
        float oo = fsig(xo[16 + 1024 + idx]);
        float ci = ftanh(xo[16 + 1536 + idx]);
        float cl = g_c[base + idx];
        float fm = sfm[l], im = sim[l], ov = fm * im;
        float cn = ov * (f * cl + ii * ci) + (fm - ov) * cl + (im - ov) * ci;
        float hn = oo * ftanh(cn);
        g_c[base + idx] = cn;
        hslot[base + idx] = hn;
        g_h[base + idx] = __float2half_rn(hn);
    }
}

// ---------------- tail kernels ---------------------------------------------------
__global__ void ldis_kernel(const float* __restrict__ dist) {
    int b = blockIdx.x * blockDim.x + threadIdx.x;
    if (b >= BDIM) return;
    float v[KWIN], s = 0.0f;
#pragma unroll
    for (int k = 0; k < KWIN; k++) { s += dist[(size_t)(TDIM - KWIN + k) * BDIM + b]; v[k] = s; }
    float m = -1e30f;
#pragma unroll
    for (int k = 0; k < KWIN; k++) m = fmaxf(m, v[k]);
    float es = 0.0f;
#pragma unroll
    for (int k = 0; k < KWIN; k++) { v[k] = expf(v[k] - m); es += v[k]; }
    float inv = 1.0f / es;
#pragma unroll
    for (int k = 0; k < KWIN; k++) g_ldis[b * KWIN + k] = v[k] * inv;
}

// local_h (bf16 hi/lo, layout (B, h*KWIN+k)) + mean over k -> g_mh
__global__ void meanlh_kernel() {
    int id = blockIdx.x * blockDim.x + threadIdx.x;
    if (id >= BDIM * HDIM) return;
    int b = id >> 9;
    int hh = id & 511;
    float acc = 0.0f;
    size_t lbase = (size_t)b * CONVK + hh * KWIN;
#pragma unroll
    for (int k = 0; k < KWIN; k++) {
        int slot = (TDIM - KWIN + k) % KWIN;
        float hv = g_hring[(size_t)slot * BDIM * HDIM + id];
        float lv = hv * g_ldis[b * KWIN + k];
        __nv_bfloat16 hi = __float2bfloat16(lv);
        g_lhhi[lbase + k] = hi;
        g_lhlo[lbase + k] = __float2bfloat16(lv - __bfloat162float(hi));
        acc += lv;
    }
    g_mh[id] = acc * (1.0f / KWIN);
}

template <int EPI>
__global__ void __launch_bounds__(256) sgemm_kernel(
    const float* __restrict__ A, const float* __restrict__ W,
    const float* __restrict__ bias, float* __restrict__ out, int M, int N, int K)
{
    __shared__ float As[8][128];
    __shared__ float Bs[8][128];
    int tid = threadIdx.x;
    int bm = blockIdx.y * 128;
    int bn = blockIdx.x * 128;
    int ty = tid >> 4, tx = tid & 15;

    float acc[8][8];
#pragma unroll
    for (int i = 0; i < 8; i++)
#pragma unroll
        for (int j = 0; j < 8; j++) acc[i][j] = 0.0f;

    int aRow = tid >> 1, aK = (tid & 1) * 4;
    int bRow = tid >> 5, bCol = (tid & 31) * 4;

    for (int k0 = 0; k0 < K; k0 += 8) {
        int gm = bm + aRow;
#pragma unroll
        for (int j = 0; j < 4; j++) {
            int gk = k0 + aK + j;
            As[aK + j][aRow] = (gm < M && gk < K) ? A[(size_t)gm * K + gk] : 0.0f;
        }
        {
            int gk = k0 + bRow;
#pragma unroll
            for (int j = 0; j < 4; j++) {
                int gn = bn + bCol + j;
                Bs[bRow][bCol + j] = (gk < K && gn < N) ? W[(size_t)gk * N + gn] : 0.0f;
            }
        }
        __syncthreads();
#pragma unroll
        for (int kk = 0; kk < 8; kk++) {
            float a[8], bb[8];
#pragma unroll
            for (int i = 0; i < 8; i++) a[i] = As[kk][ty * 8 + i];
#pragma unroll
            for (int i = 0; i < 8; i++) bb[i] = Bs[kk][tx * 8 + i];
#pragma unroll
            for (int i = 0; i < 8; i++)
#pragma unroll
                for (int j = 0; j < 8; j++) acc[i][j] += a[i] * bb[j];
        }
        __syncthreads();
    }
#pragma unroll
    for (int i = 0; i < 8; i++) {
        int gm = bm + ty * 8 + i;
        if (gm >= M) continue;
#pragma unroll
        for (int j = 0; j < 8; j++) {
            int gn = bn + tx * 8 + j;
            if (gn >= N) continue;
            float v = acc[i][j] + bias[gn];
            if (EPI == 1) v = fmaxf(v, 0.0f);
            if (EPI == 2) v = 1.0f / (1.0f + expf(-v));
            out[(size_t)gm * N + gn] = v;
        }
    }
}

// ---------------- host launcher --------------------------------------------------
extern "C" void kernel_launch(void* const* d_in, const int* in_sizes, int n_in,
                              void* d_out, int out_size) {
    const float* x      = (const float*)d_in[0];
    const float* tmv    = (const float*)d_in[1];
    const float* Wk     = (const float*)d_in[2];
    const float* bk     = (const float*)d_in[3];
    const float* Wr     = (const float*)d_in[4];
    const float* br     = (const float*)d_in[5];
    const float* Ws     = (const float*)d_in[6];
    const float* bs     = (const float*)d_in[7];
    const float* Wrs    = (const float*)d_in[8];
    const float* brs    = (const float*)d_in[9];
    const float* conv_w = (const float*)d_in[10];
    const float* conv_b = (const float*)d_in[11];
    float* out = (float*)d_out;
    float* dist_out = out + (size_t)BDIM * HDIM;   // distance region: (T, B)

    float *p_mh, *p_t1, *p_theme;
    cudaGetSymbolAddress((void**)&p_mh, g_mh);
    cudaGetSymbolAddress((void**)&p_t1, g_t1);
    cudaGetSymbolAddress((void**)&p_theme, g_theme);

    cudaFuncSetAttribute(step_mma_kernel, cudaFuncAttributeMaxDynamicSharedMemorySize,
                         SMEM_BYTES);
    cudaFuncSetAttribute(conv_mma_kernel, cudaFuncAttributeMaxDynamicSharedMemorySize,
                         CSMEM_BYTES);

    // prep (largest id space: T*B*F = 33.5M)
    size_t prep_total = (size_t)TDIM * BDIM * FDIM;
    prep_kernel<<<(unsigned)((prep_total + 255) / 256), 256>>>(x, tmv, Wk, bk, Wr, br,
                                                               conv_w);

    // recurrent scan: one-wave step GEMM (136 CTAs, 256 threads) + gating
    dim3 gstep(NPAD / NTILE, BDIM / MTILE);   // (17, 8)
    for (int t = 0; t < TDIM; t++) {
        step_mma_kernel<<<gstep, 256, SMEM_BYTES>>>(t);
        gate_kernel<<<BDIM, 256>>>(t, dist_out + (size_t)t * BDIM);
    }

    // tail
    ldis_kernel<<<(BDIM + 255) / 256, 256>>>(dist_out);
    meanlh_kernel<<<(BDIM * HDIM) / 256, 256>>>();
    sgemm_kernel<1><<<dim3(1, 16), 256>>>(p_mh, Ws, bs, p_t1, BDIM, H6, HDIM);
    sgemm_kernel<2><<<dim3(4, 16), 256>>>(p_t1, Wrs, brs, p_theme, BDIM, HDIM, H6);
    conv_mma_kernel<<<dim3(HDIM / 128, BDIM / 128), 256, CSMEM_BYTES>>>(conv_b, out);
}

// round 12
// speedup vs baseline: 1.2373x; 1.0209x over previous
#include <cuda_runtime.h>
#include <cuda_bf16.h>
#include <cuda_fp16.h>
#include <math.h>
#include <stdint.h>

#define BDIM 2048
#define TDIM 128
#define FDIM 128
#define HDIM 512
#define LDIM 8
#define KWIN 10
#define GATES 2064
#define H6 85
#define NPAD 2176            // GATES padded to 17*128
#define KPAD 640             // 128 (x) + 512 (h); dt handled as rank-1 in epilogue
#define NCHUNK 5             // K-chunks of 128: chunk0 = x, chunks 1-4 = h
#define CONVK 5120           // HDIM * KWIN
#define CONVCHUNK 80         // CONVK / 64
#define MTILE 256
#define NTILE 128
// step stage (K=128 chunk): A fp16 64K @0, B fp16 32K @65536
#define BUF_BYTES 98304
#define SMEM_BYTES (2 * BUF_BYTES)     // 192KB, 1 CTA/SM
// conv kernel keeps bf16 3-pass 128x128 tiles
#define CBUF_BYTES 65536
#define CSMEM_BYTES (3 * CBUF_BYTES)

// ---------------- device globals (static; no runtime allocation) ---------------
__device__ __align__(256) __half g_W[(size_t)NPAD * KPAD];     // W^T fp16, (N,K)
__device__ __align__(256) __half g_xT[(size_t)TDIM * BDIM * FDIM]; // x (T,B,F) fp16
__device__ __align__(256) __half g_h[BDIM * HDIM];             // hidden state fp16
__device__ __align__(256) __nv_bfloat16 g_lhhi[(size_t)BDIM * CONVK]; // local_h hi
__device__ __align__(256) __nv_bfloat16 g_lhlo[(size_t)BDIM * CONVK];
__device__ __align__(256) __nv_bfloat16 g_cwhi[(size_t)HDIM * CONVK]; // conv_w
__device__ __align__(256) __nv_bfloat16 g_cwlo[(size_t)HDIM * CONVK];
__device__ __align__(256) float g_dt[TDIM * BDIM];    // time transposed (T,B) fp32
__device__ __align__(256) float g_Wdt[NPAD];          // dt row fp32
__device__ __align__(256) float g_bc[NPAD];
__device__ __align__(256) float g_xo[(size_t)BDIM * NPAD];
__device__ __align__(256) float g_c[BDIM * HDIM];
__device__ __align__(256) float g_hring[KWIN * BDIM * HDIM];
__device__ __align__(256) float g_ldis[BDIM * KWIN];
__device__ __align__(256) float g_mh[BDIM * HDIM];
__device__ __align__(256) float g_t1[BDIM * H6];
__device__ __align__(256) float g_theme[BDIM * HDIM];

__device__ __forceinline__ float fsig(float x) { return 1.0f / (1.0f + __expf(-x)); }
__device__ __forceinline__ float ftanh(float x) {
    return 1.0f - 2.0f / (__expf(2.0f * x) + 1.0f);
}

// ---------------- PTX helpers (compute_103-legal, sm_80-era) --------------------
__device__ __forceinline__ uint32_t smem_u32(const void* p) {
    uint32_t a;
    asm("{ .reg .u64 t; cvta.to.shared.u64 t, %1; cvt.u32.u64 %0, t; }" : "=r"(a) : "l"(p));
    return a;
}
__device__ __forceinline__ void cp16(uint32_t saddr, const void* g) {
    asm volatile("cp.async.cg.shared.global [%0], [%1], 16;" :: "r"(saddr), "l"(g)
                 : "memory");
}
#define CP_COMMIT() asm volatile("cp.async.commit_group;" ::: "memory")
#define CP_WAIT0()  asm volatile("cp.async.wait_group 0;" ::: "memory")
#define CP_WAIT1()  asm volatile("cp.async.wait_group 1;" ::: "memory")

__device__ __forceinline__ void ldsm_x4(uint32_t* r, uint32_t addr) {
    asm volatile("ldmatrix.sync.aligned.m8n8.x4.shared.b16 {%0,%1,%2,%3}, [%4];"
                 : "=r"(r[0]), "=r"(r[1]), "=r"(r[2]), "=r"(r[3]) : "r"(addr));
}
__device__ __forceinline__ void ldsm_x2(uint32_t* r, uint32_t addr) {
    asm volatile("ldmatrix.sync.aligned.m8n8.x2.shared.b16 {%0,%1}, [%2];"
                 : "=r"(r[0]), "=r"(r[1]) : "r"(addr));
}
__device__ __forceinline__ void mma_f16(float* d, const uint32_t* a, const uint32_t* b) {
    asm volatile(
        "mma.sync.aligned.m16n8k16.row.col.f32.f16.f16.f32 "
        "{%0,%1,%2,%3}, {%4,%5,%6,%7}, {%8,%9}, {%0,%1,%2,%3};"
        : "+f"(d[0]), "+f"(d[1]), "+f"(d[2]), "+f"(d[3])
        : "r"(a[0]), "r"(a[1]), "r"(a[2]), "r"(a[3]), "r"(b[0]), "r"(b[1]));
}
__device__ __forceinline__ void mma_bf16(float* d, const uint32_t* a, const uint32_t* b) {
    asm volatile(
        "mma.sync.aligned.m16n8k16.row.col.f32.bf16.bf16.f32 "
        "{%0,%1,%2,%3}, {%4,%5,%6,%7}, {%8,%9}, {%0,%1,%2,%3};"
        : "+f"(d[0]), "+f"(d[1]), "+f"(d[2]), "+f"(d[3])
        : "r"(a[0]), "r"(a[1]), "r"(a[2]), "r"(a[3]), "r"(b[0]), "r"(b[1]));
}

// ---------------- prep ----------------------------------------------------------
__global__ void prep_kernel(const float* __restrict__ x, const float* __restrict__ tmv,
                            const float* __restrict__ Wk, const float* __restrict__ bk,
                            const float* __restrict__ Wr, const float* __restrict__ br,
                            const float* __restrict__ conv_w) {
    size_t id = (size_t)blockIdx.x * blockDim.x + threadIdx.x;
    if (id < (size_t)NPAD * KPAD) {
        int n = (int)(id / KPAD), k = (int)(id % KPAD);
        float v = 0.0f;
        if (n < GATES)
            v = (k < FDIM) ? Wk[k * GATES + n] : Wr[(k - FDIM) * GATES + n];
        g_W[id] = __float2half_rn(v);
    }
    if (id < NPAD) {
        g_bc[id]  = (id < GATES) ? bk[id] + br[id] : 0.0f;
        g_Wdt[id] = (id < GATES) ? Wk[(size_t)FDIM * GATES + id] +
                                   Wr[(size_t)HDIM * GATES + id] : 0.0f;
    }
    if (id < (size_t)TDIM * BDIM * FDIM) {
        int f = (int)(id & (FDIM - 1));
        int b = (int)((id >> 7) & (BDIM - 1));
        int t = (int)(id >> 18);
        g_xT[id] = __float2half_rn(x[((size_t)b * TDIM + t) * FDIM + f]);
    }
    if (id < (size_t)TDIM * BDIM) {
        int b = (int)(id % BDIM), t = (int)(id / BDIM);
        g_dt[id] = tmv[(size_t)b * TDIM + t];
    }
    if (id < (size_t)BDIM * HDIM) {
        g_c[id] = 0.0f;
        g_h[id] = __float2half_rn(0.0f);
    }
    if (id < (size_t)HDIM * CONVK) {
        float v = conv_w[id];                       // already (512, 5120) K-major
        __nv_bfloat16 hi = __float2bfloat16(v);
        g_cwhi[id] = hi;
        g_cwlo[id] = __float2bfloat16(v - __bfloat162float(hi));
    }
}

// ---------------- step chunk loader (K=128 chunk; 256B rows, 16 segments) -------
// chunk 0 = x[t] (F=128), chunks 1-4 = h[:, (c-1)*128 : c*128]
__device__ __forceinline__ void step_load_chunk(uint32_t sb, int buf, int c, int t,
                                                int bm, int bn) {
    int tid = threadIdx.x;
    uint32_t base = sb + (uint32_t)buf * BUF_BYTES;
    // A: 256 rows x 128 fp16 = 4096 16B vectors
#pragma unroll
    for (int it = 0; it < 16; ++it) {
        int idx = tid + it * 256;
        int r = idx >> 4, s = idx & 15;
        uint32_t soff = (uint32_t)(r * 256 + ((s ^ (r & 7)) << 4));
        const __half* gp;
        if (c == 0)
            gp = g_xT + ((size_t)t * BDIM + bm + r) * FDIM + s * 8;
        else
            gp = g_h + (size_t)(bm + r) * HDIM + (c - 1) * 128 + s * 8;
        cp16(base + soff, gp);
    }
    // B: 128 rows x 128 fp16 = 2048 vectors
#pragma unroll
    for (int it = 0; it < 8; ++it) {
        int idx = tid + it * 256;
        int r = idx >> 4, s = idx & 15;
        uint32_t soff = (uint32_t)(r * 256 + ((s ^ (r & 7)) << 4));
        size_t go = (size_t)(bn + r) * KPAD + c * 128 + s * 8;
        cp16(base + 65536 + soff, g_W + go);
    }
}

// ---------------- compute one K=128 chunk, 64x64 warp tile (single pass) --------
// 8 warps = 4 (m) x 2 (n). acc[mi=4][ni=8][4].
__device__ __forceinline__ void step_compute_chunk(uint32_t base, int warp_m, int warp_n,
                                                   int lane, float (*acc)[8][4]) {
    uint32_t Ab = base, Bb = base + 65536;
    int arow_off = (lane & 7) + ((lane & 8) ? 8 : 0);
    int bL = lane & 15;
#pragma unroll
    for (int ks = 0; ks < 8; ++ks) {
        uint32_t ah[4][4];
        int aseg = 2 * ks + ((lane & 16) ? 1 : 0);
        int bseg = 2 * ks + ((bL & 8) ? 1 : 0);
#pragma unroll
        for (int mi = 0; mi < 4; ++mi) {
            int r = warp_m * 64 + mi * 16 + arow_off;
            uint32_t off = (uint32_t)(r * 256 + ((aseg ^ (r & 7)) << 4));
            ldsm_x4(ah[mi], Ab + off);
        }
#pragma unroll
        for (int ni = 0; ni < 8; ++ni) {
            uint32_t bb[2];
            int r = warp_n * 64 + ni * 8 + (bL & 7);
            uint32_t off = (uint32_t)(r * 256 + ((bseg ^ (r & 7)) << 4));
            ldsm_x2(bb, Bb + off);
#pragma unroll
            for (int mi = 0; mi < 4; ++mi) mma_f16(acc[mi][ni], ah[mi], bb);
        }
    }
}

// ---------------- per-step GEMM: xo = [x_t|h] @ W + dt*Wdt + bc -----------------
// Tile 256x128, 256 threads, grid (17, 8) = 136 CTAs; 2-stage, 5 K-chunks.
__global__ void __launch_bounds__(256, 1) step_mma_kernel(int t) {
    extern __shared__ char smem[];
    uint32_t sb = smem_u32(smem);
    int tid = threadIdx.x, wid = tid >> 5, lane = tid & 31;
    int warp_m = wid >> 1, warp_n = wid & 1;
    int bn = blockIdx.x * NTILE, bm = blockIdx.y * MTILE;

    float acc[4][8][4];
#pragma unroll
    for (int i = 0; i < 4; ++i)
#pragma unroll
        for (int j = 0; j < 8; ++j)
#pragma unroll
            for (int k = 0; k < 4; ++k) acc[i][j][k] = 0.0f;

    step_load_chunk(sb, 0, 0, t, bm, bn);
    CP_COMMIT();
    for (int c = 0; c < NCHUNK; ++c) {
        CP_WAIT0();
        __syncthreads();
        // safe to overwrite buffer (c+1)&1: all warps finished chunk c-1's compute
        if (c + 1 < NCHUNK) {
            step_load_chunk(sb, (c + 1) & 1, c + 1, t, bm, bn);
            CP_COMMIT();
        }
        step_compute_chunk(sb + (uint32_t)(c & 1) * BUF_BYTES, warp_m, warp_n, lane, acc);
    }

    // epilogue: acc + bias + dt*Wdt -> g_xo
    int gr = lane >> 2, gc = (lane & 3) * 2;
#pragma unroll
    for (int mi = 0; mi < 4; ++mi) {
        int row0 = bm + warp_m * 64 + mi * 16 + gr;
        float dt0 = g_dt[t * BDIM + row0];
        float dt8 = g_dt[t * BDIM + row0 + 8];
#pragma unroll
        for (int ni = 0; ni < 8; ++ni) {
            int col = bn + warp_n * 64 + ni * 8 + gc;
            float b0 = g_bc[col], b1 = g_bc[col + 1];
            float w0 = g_Wdt[col], w1 = g_Wdt[col + 1];
            float2 v0 = make_float2(acc[mi][ni][0] + b0 + dt0 * w0,
                                    acc[mi][ni][1] + b1 + dt0 * w1);
            float2 v1 = make_float2(acc[mi][ni][2] + b0 + dt8 * w0,
                                    acc[mi][ni][3] + b1 + dt8 * w1);
            *(float2*)&g_xo[(size_t)row0 * NPAD + col] = v0;
            *(float2*)&g_xo[(size_t)(row0 + 8) * NPAD + col] = v1;
        }
    }
}

// ---------------- conv tail: bf16 3-pass, 128x128 tiles (grid 4x16) -------------
__device__ __forceinline__ void conv_load_chunk(uint32_t sb, int buf, int c,
                                                int bm, int bn) {
    int tid = threadIdx.x;
    uint32_t base = sb + (uint32_t)buf * CBUF_BYTES;
#pragma unroll
    for (int it = 0; it < 4; ++it) {
        int idx = tid + it * 256;
        int r = idx >> 3, s = idx & 7;
        uint32_t soff = (uint32_t)(r * 128 + ((s ^ (r & 7)) << 4));
        size_t go = (size_t)(bm + r) * CONVK + c * 64 + s * 8;
        cp16(base + soff, g_lhhi + go);
        cp16(base + 16384 + soff, g_lhlo + go);
    }
#pragma unroll
    for (int it = 0; it < 4; ++it) {
        int idx = tid + it * 256;
        int r = idx >> 3, s = idx & 7;
        uint32_t soff = (uint32_t)(r * 128 + ((s ^ (r & 7)) << 4));
        size_t go = (size_t)(bn + r) * CONVK + c * 64 + s * 8;
        cp16(base + 32768 + soff, g_cwhi + go);
        cp16(base + 49152 + soff, g_cwlo + go);
    }
}

__device__ __forceinline__ void conv_compute_chunk(uint32_t base, int warp_m, int warp_n,
                                                   int lane, float (*acc)[4][4]) {
    uint32_t Ahi = base, Alo = base + 16384, Bhi = base + 32768, Blo = base + 49152;
    int arow_off = (lane & 7) + ((lane & 8) ? 8 : 0);
    int bL = lane & 15;
#pragma unroll
    for (int ks = 0; ks < 4; ++ks) {
        uint32_t ah[4][4], al_[4][4], bh[4][2], bl_[4][2];
        int aseg = 2 * ks + ((lane & 16) ? 1 : 0);
        int bseg = 2 * ks + ((bL & 8) ? 1 : 0);
#pragma unroll
        for (int mi = 0; mi < 4; ++mi) {
            int r = warp_m * 64 + mi * 16 + arow_off;
            uint32_t off = (uint32_t)(r * 128 + ((aseg ^ (r & 7)) << 4));
            ldsm_x4(ah[mi], Ahi + off);
            ldsm_x4(al_[mi], Alo + off);
        }
#pragma unroll
        for (int ni = 0; ni < 4; ++ni) {
            int r = warp_n * 32 + ni * 8 + (bL & 7);
            uint32_t off = (uint32_t)(r * 128 + ((bseg ^ (r & 7)) << 4));
            ldsm_x2(bh[ni], Bhi + off);
            ldsm_x2(bl_[ni], Blo + off);
        }
#pragma unroll
        for (int mi = 0; mi < 4; ++mi)
#pragma unroll
            for (int ni = 0; ni < 4; ++ni) {
                mma_bf16(acc[mi][ni], ah[mi], bh[ni]);
                mma_bf16(acc[mi][ni], al_[mi], bh[ni]);
                mma_bf16(acc[mi][ni], ah[mi], bl_[ni]);
            }
    }
}

__global__ void __launch_bounds__(256, 1) conv_mma_kernel(const float* __restrict__ cb,
                                                          float* __restrict__ out) {
    extern __shared__ char smem[];
    uint32_t sb = smem_u32(smem);
    int tid = threadIdx.x, wid = tid >> 5, lane = tid & 31;
    int warp_m = wid >> 2, warp_n = wid & 3;
    int bn = blockIdx.x * 128, bm = blockIdx.y * 128;

    float acc[4][4][4];
#pragma unroll
    for (int i = 0; i < 4; ++i)
#pragma unroll
        for (int j = 0; j < 4; ++j)
#pragma unroll
            for (int k = 0; k < 4; ++k) acc[i][j][k] = 0.0f;

    conv_load_chunk(sb, 0, 0, bm, bn); CP_COMMIT();
    conv_load_chunk(sb, 1, 1, bm, bn); CP_COMMIT();
    for (int c = 0; c < CONVCHUNK; ++c) {
        if (c + 1 < CONVCHUNK) { CP_WAIT1(); } else { CP_WAIT0(); }
        __syncthreads();
        if (c + 2 < CONVCHUNK) {
            conv_load_chunk(sb, (c + 2) % 3, c + 2, bm, bn);
            CP_COMMIT();
        }
        conv_compute_chunk(sb + (uint32_t)(c % 3) * CBUF_BYTES, warp_m, warp_n, lane, acc);
    }

    int gr = lane >> 2, gc = (lane & 3) * 2;
#pragma unroll
    for (int mi = 0; mi < 4; ++mi) {
        int row0 = bm + warp_m * 64 + mi * 16 + gr;
#pragma unroll
        for (int ni = 0; ni < 4; ++ni) {
            int col = bn + warp_n * 32 + ni * 8 + gc;
            float b0 = cb[col], b1 = cb[col + 1];
            float2 v0, v1;
            v0.x = g_theme[(size_t)row0 * HDIM + col] * (acc[mi][ni][0] + b0);
            v0.y = g_theme[(size_t)row0 * HDIM + col + 1] * (acc[mi][ni][1] + b1);
            v1.x = g_theme[(size_t)(row0 + 8) * HDIM + col] * (acc[mi][ni][2] + b0);
            v1.y = g_theme[(size_t)(row0 + 8) * HDIM + col + 1] * (acc[mi][ni][3] + b1);
            *(float2*)&out[(size_t)row0 * HDIM + col] = v0;
            *(float2*)&out[(size_t)(row0 + 8) * HDIM + col] = v1;
        }
    }
}

// ---------------- per-step gating (fast-math MUFU transcendental paths) ---------
__global__ void gate_kernel(int t, float* __restrict__ dist_out) {
    int b = blockIdx.x;
    int tid = threadIdx.x;
    __shared__ float sfm[LDIM], sim[LDIM];
    const float* xo = g_xo + (size_t)b * NPAD;

    if (tid == 0) {
        float z[LDIM], m = -1e30f;
#pragma unroll
        for (int l = 0; l < LDIM; l++) { z[l] = xo[l]; m = fmaxf(m, z[l]); }
        float s = 0.0f;
#pragma unroll
        for (int l = 0; l < LDIM; l++) { z[l] = __expf(z[l] - m); s += z[l]; }
        float inv = 1.0f / s, cs = 0.0f, dsum = 0.0f;
#pragma unroll
        for (int l = 0; l < LDIM; l++) { cs += z[l] * inv; sfm[l] = cs; dsum += cs; }
        dist_out[b] = 1.0f - dsum * (1.0f / LDIM);
    }
    if (tid == 32) {
        float z[LDIM], m = -1e30f;
#pragma unroll
        for (int l = 0; l < LDIM; l++) { z[l] = xo[LDIM + l]; m = fmaxf(m, z[l]); }
        float s = 0.0f;
#pragma unroll
        for (int l = 0; l < LDIM; l++) { z[l] = __expf(z[l] - m); s += z[l]; }
        float inv = 1.0f / s, cs = 0.0f;
#pragma unroll
        for (int l = LDIM - 1; l >= 0; l--) { cs += z[l] * inv; sim[l] = cs; }
    }
    __syncthreads();

    float* hslot = g_hring + (size_t)(t % KWIN) * BDIM * HDIM;
    int base = b * HDIM;
    for (int idx = tid; idx < HDIM; idx += blockDim.x) {
        int l = idx >> 6;
        float f  = fsig(xo[16 + idx]);
        float ii = fsig(xo[16 + 512 + idx]);
        float oo = fsig(xo[16 + 1024 + idx]);
        float ci = ftanh(xo[16 + 1536 + idx]);
        float cl = g_c[base + idx];
        float fm = sfm[l], im = sim[l], ov = fm * im;
        float cn = ov * (f * cl + ii * ci) + (fm - ov) * cl + (im - ov) * ci;
        float hn = oo * ftanh(cn);
        g_c[base + idx] = cn;
        hslot[base + idx] = hn;
        g_h[base + idx] = __float2half_rn(hn);
    }
}

// ---------------- tail kernels ---------------------------------------------------
__global__ void ldis_kernel(const float* __restrict__ dist) {
    int b = blockIdx.x * blockDim.x + threadIdx.x;
    if (b >= BDIM) return;
    float v[KWIN], s = 0.0f;
#pragma unroll
    for (int k = 0; k < KWIN; k++) { s += dist[(size_t)(TDIM - KWIN + k) * BDIM + b]; v[k] = s; }
    float m = -1e30f;
#pragma unroll
    for (int k = 0; k < KWIN; k++) m = fmaxf(m, v[k]);
    float es = 0.0f;
#pragma unroll
    for (int k = 0; k < KWIN; k++) { v[k] = expf(v[k] - m); es += v[k]; }
    float inv = 1.0f / es;
#pragma unroll
    for (int k = 0; k < KWIN; k++) g_ldis[b * KWIN + k] = v[k] * inv;
}

// local_h (bf16 hi/lo, layout (B, h*KWIN+k)) + mean over k -> g_mh
__global__ void meanlh_kernel() {
    int id = blockIdx.x * blockDim.x + threadIdx.x;
    if (id >= BDIM * HDIM) return;
    int b = id >> 9;
    int hh = id & 511;
    float acc = 0.0f;
    size_t lbase = (size_t)b * CONVK + hh * KWIN;
#pragma unroll
    for (int k = 0; k < KWIN; k++) {
        int slot = (TDIM - KWIN + k) % KWIN;
        float hv = g_hring[(size_t)slot * BDIM * HDIM + id];
        float lv = hv * g_ldis[b * KWIN + k];
        __nv_bfloat16 hi = __float2bfloat16(lv);
        g_lhhi[lbase + k] = hi;
        g_lhlo[lbase + k] = __float2bfloat16(lv - __bfloat162float(hi));
        acc += lv;
    }
    g_mh[id] = acc * (1.0f / KWIN);
}

template <int EPI>
__global__ void __launch_bounds__(256) sgemm_kernel(
    const float* __restrict__ A, const float* __restrict__ W,
    const float* __restrict__ bias, float* __restrict__ out, int M, int N, int K)
{
    __shared__ float As[8][128];
    __shared__ float Bs[8][128];
    int tid = threadIdx.x;
    int bm = blockIdx.y * 128;
    int bn = blockIdx.x * 128;
    int ty = tid >> 4, tx = tid & 15;

    float acc[8][8];
#pragma unroll
    for (int i = 0; i < 8; i++)
#pragma unroll
        for (int j = 0; j < 8; j++) acc[i][j] = 0.0f;

    int aRow = tid >> 1, aK = (tid & 1) * 4;
    int bRow = tid >> 5, bCol = (tid & 31) * 4;

    for (int k0 = 0; k0 < K; k0 += 8) {
        int gm = bm + aRow;
#pragma unroll
        for (int j = 0; j < 4; j++) {
            int gk = k0 + aK + j;
            As[aK + j][aRow] = (gm < M && gk < K) ? A[(size_t)gm * K + gk] : 0.0f;
        }
        {
            int gk = k0 + bRow;
#pragma unroll
            for (int j = 0; j < 4; j++) {
                int gn = bn + bCol + j;
                Bs[bRow][bCol + j] = (gk < K && gn < N) ? W[(size_t)gk * N + gn] : 0.0f;
            }
        }
        __syncthreads();
#pragma unroll
        for (int kk = 0; kk < 8; kk++) {
            float a[8], bb[8];
#pragma unroll
            for (int i = 0; i < 8; i++) a[i] = As[kk][ty * 8 + i];
#pragma unroll
            for (int i = 0; i < 8; i++) bb[i] = Bs[kk][tx * 8 + i];
#pragma unroll
            for (int i = 0; i < 8; i++)
#pragma unroll
                for (int j = 0; j < 8; j++) acc[i][j] += a[i] * bb[j];
        }
        __syncthreads();
    }
#pragma unroll
    for (int i = 0; i < 8; i++) {
        int gm = bm + ty * 8 + i;
        if (gm >= M) continue;
#pragma unroll
        for (int j = 0; j < 8; j++) {
            int gn = bn + tx * 8 + j;
            if (gn >= N) continue;
            float v = acc[i][j] + bias[gn];
            if (EPI == 1) v = fmaxf(v, 0.0f);
            if (EPI == 2) v = 1.0f / (1.0f + expf(-v));
            out[(size_t)gm * N + gn] = v;
        }
    }
}

// ---------------- host launcher --------------------------------------------------
extern "C" void kernel_launch(void* const* d_in, const int* in_sizes, int n_in,
                              void* d_out, int out_size) {
    const float* x      = (const float*)d_in[0];
    const float* tmv    = (const float*)d_in[1];
    const float* Wk     = (const float*)d_in[2];
    const float* bk     = (const float*)d_in[3];
    const float* Wr     = (const float*)d_in[4];
    const float* br     = (const float*)d_in[5];
    const float* Ws     = (const float*)d_in[6];
    const float* bs     = (const float*)d_in[7];
    const float* Wrs    = (const float*)d_in[8];
    const float* brs    = (const float*)d_in[9];
    const float* conv_w = (const float*)d_in[10];
    const float* conv_b = (const float*)d_in[11];
    float* out = (float*)d_out;
    float* dist_out = out + (size_t)BDIM * HDIM;   // distance region: (T, B)

    float *p_mh, *p_t1, *p_theme;
    cudaGetSymbolAddress((void**)&p_mh, g_mh);
    cudaGetSymbolAddress((void**)&p_t1, g_t1);
    cudaGetSymbolAddress((void**)&p_theme, g_theme);

    cudaFuncSetAttribute(step_mma_kernel, cudaFuncAttributeMaxDynamicSharedMemorySize,
                         SMEM_BYTES);
    cudaFuncSetAttribute(conv_mma_kernel, cudaFuncAttributeMaxDynamicSharedMemorySize,
                         CSMEM_BYTES);

    // prep (largest id space: T*B*F = 33.5M)
    size_t prep_total = (size_t)TDIM * BDIM * FDIM;
    prep_kernel<<<(unsigned)((prep_total + 255) / 256), 256>>>(x, tmv, Wk, bk, Wr, br,
                                                               conv_w);

    // recurrent scan: one-wave step GEMM (136 CTAs, 256 threads, 5 K-chunks) + gate
    dim3 gstep(NPAD / NTILE, BDIM / MTILE);   // (17, 8)
    for (int t = 0; t < TDIM; t++) {
        step_mma_kernel<<<gstep, 256, SMEM_BYTES>>>(t);
        gate_kernel<<<BDIM, 256>>>(t, dist_out + (size_t)t * BDIM);
    }

    // tail
    ldis_kernel<<<(BDIM + 255) / 256, 256>>>(dist_out);
    meanlh_kernel<<<(BDIM * HDIM) / 256, 256>>>();
    sgemm_kernel<1><<<dim3(1, 16), 256>>>(p_mh, Ws, bs, p_t1, BDIM, H6, HDIM);
    sgemm_kernel<2><<<dim3(4, 16), 256>>>(p_t1, Wrs, brs, p_theme, BDIM, HDIM, H6);
    conv_mma_kernel<<<dim3(HDIM / 128, BDIM / 128), 256, CSMEM_BYTES>>>(conv_b, out);
}